// round 5
// baseline (speedup 1.0000x reference)
#include <cuda_runtime.h>
#include <cstdint>

#define N_NODES 50000
#define N_EDGES 800000
#define D_IN    256
#define D_OUT   64
#define NEG_SLOPE 0.2f

// Scratch: support = x @ W^T + b   [N_NODES, D_OUT]
__device__ float g_support[N_NODES * D_OUT];
// Precomputed tf32 hi/lo splits of W
__device__ uint32_t g_whi[D_OUT * D_IN];
__device__ uint32_t g_wlo[D_OUT * D_IN];

// ---------------------------------------------------------------------------
// TF32 helpers
// ---------------------------------------------------------------------------
__device__ __forceinline__ void tf32_split(float f, uint32_t& hi, uint32_t& lo) {
    uint32_t h;
    asm("cvt.rna.tf32.f32 %0, %1;" : "=r"(h) : "f"(f));
    float hf = __uint_as_float(h);
    float lf = f - hf;
    asm("cvt.rna.tf32.f32 %0, %1;" : "=r"(lo) : "f"(lf));
    hi = h;
}

__device__ __forceinline__ void mma_tf32(float c[4], const uint32_t a[4], const uint32_t b[2]) {
    asm volatile(
        "mma.sync.aligned.m16n8k8.row.col.f32.tf32.tf32.f32 "
        "{%0,%1,%2,%3}, {%4,%5,%6,%7}, {%8,%9}, {%0,%1,%2,%3};"
        : "+f"(c[0]), "+f"(c[1]), "+f"(c[2]), "+f"(c[3])
        : "r"(a[0]), "r"(a[1]), "r"(a[2]), "r"(a[3]), "r"(b[0]), "r"(b[1]));
}

// ---------------------------------------------------------------------------
// Kernel 0: precompute tf32 splits of W (tiny; 16384 elems)
// ---------------------------------------------------------------------------
__global__ void wsplit_kernel(const float* __restrict__ W,
                              uint32_t* __restrict__ whi,
                              uint32_t* __restrict__ wlo) {
    int i = blockIdx.x * blockDim.x + threadIdx.x;
    if (i < D_OUT * D_IN) {
        uint32_t h, l;
        tf32_split(__ldg(&W[i]), h, l);
        whi[i] = h; wlo[i] = l;
    }
}

// ---------------------------------------------------------------------------
// Kernel 1: support = x @ W^T + b  via tf32 tensor cores (3xTF32 accuracy)
//   Block: 256 threads (8 warps). Warp: 16 rows x 64 cols. Block: 128 rows.
//   x staged per K_CHUNK; W hi/lo splits staged pre-split. smem = 36.9 KB.
// ---------------------------------------------------------------------------
#define K_CHUNK 32
#define XPAD 36   // 36 mod 32 == 4 -> conflict-free quads; 16B-aligned rows

__global__ __launch_bounds__(256) void gemm_tf32_kernel(
    const float* __restrict__ x,
    const uint32_t* __restrict__ whi,
    const uint32_t* __restrict__ wlo,
    const float* __restrict__ bias,
    float* __restrict__ support)
{
    __shared__ float    xs[128][XPAD];  // [row][k]
    __shared__ uint32_t wh[64][XPAD];   // [out][k] tf32 hi
    __shared__ uint32_t wl[64][XPAD];   // [out][k] tf32 lo

    const int tid  = threadIdx.x;
    const int warp = tid >> 5;
    const int lane = tid & 31;
    const int gq   = lane >> 2;   // 0..7 (row group)
    const int tq   = lane & 3;    // 0..3 (col group)
    const int row_base = blockIdx.x * 128;

    float acc[8][4];
    #pragma unroll
    for (int nt = 0; nt < 8; nt++)
        #pragma unroll
        for (int j = 0; j < 4; j++) acc[nt][j] = 0.f;

    for (int kt = 0; kt < D_IN; kt += K_CHUNK) {
        // Stage x tile [128][32]: 1024 float4, 4 per thread
        #pragma unroll
        for (int i = 0; i < 4; i++) {
            int idx = tid + i * 256;
            int r   = idx >> 3;
            int c4  = idx & 7;
            int gr  = row_base + r;
            float4 v = make_float4(0.f, 0.f, 0.f, 0.f);
            if (gr < N_NODES)
                v = *(const float4*)&x[(size_t)gr * D_IN + kt + c4 * 4];
            *(float4*)&xs[r][c4 * 4] = v;
        }
        // Stage W hi/lo tiles [64][32]: 512 uint4 each, 2 per thread each
        #pragma unroll
        for (int i = 0; i < 2; i++) {
            int idx = tid + i * 256;
            int r   = idx >> 3;
            int c4  = idx & 7;
            *(uint4*)&wh[r][c4 * 4] = *(const uint4*)&whi[(size_t)r * D_IN + kt + c4 * 4];
            *(uint4*)&wl[r][c4 * 4] = *(const uint4*)&wlo[(size_t)r * D_IN + kt + c4 * 4];
        }
        __syncthreads();

        #pragma unroll
        for (int k8 = 0; k8 < K_CHUNK; k8 += 8) {
            // A fragment (m16n8k8 row-major)
            const int r0 = warp * 16 + gq;
            float af[4];
            af[0] = xs[r0    ][k8 + tq];
            af[1] = xs[r0 + 8][k8 + tq];
            af[2] = xs[r0    ][k8 + tq + 4];
            af[3] = xs[r0 + 8][k8 + tq + 4];
            uint32_t ah[4], al[4];
            #pragma unroll
            for (int j = 0; j < 4; j++) tf32_split(af[j], ah[j], al[j]);

            #pragma unroll
            for (int nt = 0; nt < 8; nt++) {
                const int n0 = nt * 8 + gq;
                uint32_t bh[2], bl[2];
                bh[0] = wh[n0][k8 + tq];
                bh[1] = wh[n0][k8 + tq + 4];
                bl[0] = wl[n0][k8 + tq];
                bl[1] = wl[n0][k8 + tq + 4];
                mma_tf32(acc[nt], ah, bh);   // hi*hi
                mma_tf32(acc[nt], ah, bl);   // hi*lo
                mma_tf32(acc[nt], al, bh);   // lo*hi
            }
        }
        __syncthreads();
    }

    // Epilogue
    const int r_lo = row_base + warp * 16 + gq;
    const int r_hi = r_lo + 8;
    #pragma unroll
    for (int nt = 0; nt < 8; nt++) {
        int c0 = nt * 8 + tq * 2;
        float bx = bias[c0], by = bias[c0 + 1];
        if (r_lo < N_NODES) {
            float2 v = make_float2(acc[nt][0] + bx, acc[nt][1] + by);
            *(float2*)&support[(size_t)r_lo * D_OUT + c0] = v;
        }
        if (r_hi < N_NODES) {
            float2 v = make_float2(acc[nt][2] + bx, acc[nt][3] + by);
            *(float2*)&support[(size_t)r_hi * D_OUT + c0] = v;
        }
    }
}

// ---------------------------------------------------------------------------
// Kernel 2: node-centric aggregation + LeakyReLU.
//   Warp per node. Segment found via in-warp binary search on sorted edge_dst
//   (lane 0 -> lower_bound(node), lane 1 -> lower_bound(node+1)).
//   Lane owns columns {lane, lane+32}. No atomics, direct store.
// ---------------------------------------------------------------------------
__global__ __launch_bounds__(256) void agg_node_kernel(
    const int*   __restrict__ edge_src,
    const int*   __restrict__ edge_dst,
    const float* __restrict__ edge_val,
    const float* __restrict__ support,
    float*       __restrict__ out)
{
    const int node = (blockIdx.x * blockDim.x + threadIdx.x) >> 5;
    const int lane = threadIdx.x & 31;
    if (node >= N_NODES) return;

    // Binary search bounds (fixed 20 iterations; both lanes run in lockstep)
    int bound = 0;
    if (lane < 2) {
        int target = node + lane;
        int lo = 0, hi = N_EDGES;
        while (lo < hi) {
            int mid = (lo + hi) >> 1;
            if (__ldg(&edge_dst[mid]) < target) lo = mid + 1;
            else hi = mid;
        }
        bound = lo;
    }
    const int beg = __shfl_sync(0xffffffff, bound, 0);
    const int end = __shfl_sync(0xffffffff, bound, 1);

    float acc0 = 0.f, acc1 = 0.f;
    #pragma unroll 8
    for (int e = beg; e < end; e++) {
        const int   s = __ldg(&edge_src[e]);   // warp-uniform broadcast
        const float v = __ldg(&edge_val[e]);
        const float* srow = &support[(size_t)s * D_OUT];
        acc0 += v * __ldg(&srow[lane]);
        acc1 += v * __ldg(&srow[lane + 32]);
    }
    acc0 = (acc0 >= 0.f) ? acc0 : NEG_SLOPE * acc0;
    acc1 = (acc1 >= 0.f) ? acc1 : NEG_SLOPE * acc1;
    out[(size_t)node * D_OUT + lane]      = acc0;
    out[(size_t)node * D_OUT + lane + 32] = acc1;
}

// ---------------------------------------------------------------------------
// Launch
// ---------------------------------------------------------------------------
extern "C" void kernel_launch(void* const* d_in, const int* in_sizes, int n_in,
                              void* d_out, int out_size) {
    const float* x        = (const float*)d_in[0];
    const float* W        = (const float*)d_in[1];
    const float* b        = (const float*)d_in[2];
    const int*   edge_src = (const int*)  d_in[3];
    const int*   edge_dst = (const int*)  d_in[4];
    const float* edge_val = (const float*)d_in[5];
    float* out = (float*)d_out;

    float* support;
    cudaGetSymbolAddress((void**)&support, g_support);
    uint32_t* whi;
    cudaGetSymbolAddress((void**)&whi, g_whi);
    uint32_t* wlo;
    cudaGetSymbolAddress((void**)&wlo, g_wlo);

    // 0. split W into tf32 hi/lo
    wsplit_kernel<<<(D_OUT * D_IN + 255) / 256, 256>>>(W, whi, wlo);

    // 1. tf32 tensor-core projection
    gemm_tf32_kernel<<<(N_NODES + 127) / 128, 256>>>(x, whi, wlo, b, support);

    // 2. fused aggregation + LeakyReLU (warp per node, self-located segments)
    const int n_blocks = (N_NODES * 32 + 255) / 256;
    agg_node_kernel<<<n_blocks, 256>>>(edge_src, edge_dst, edge_val, support, out);
}

// round 6
// speedup vs baseline: 1.3810x; 1.3810x over previous
#include <cuda_runtime.h>
#include <cstdint>

#define N_NODES 50000
#define N_EDGES 800000
#define D_IN    256
#define D_OUT   64
#define NEG_SLOPE 0.2f

// Scratch: support = x @ W^T + b   [N_NODES, D_OUT]
__device__ float g_support[N_NODES * D_OUT];
// CSR row pointers for sorted edge_dst
__device__ int g_rowptr[N_NODES + 1];
// W tf32 splits in fragment-paired layout: [n][kb][tq] -> uint2{w[kb*8+tq], w[kb*8+tq+4]}
__device__ uint2 g_whp[D_OUT * (D_IN / 8) * 4];   // 8192 uint2
__device__ uint2 g_wlp[D_OUT * (D_IN / 8) * 4];

// ---------------------------------------------------------------------------
// TF32 helpers
// ---------------------------------------------------------------------------
__device__ __forceinline__ void tf32_split(float f, uint32_t& hi, uint32_t& lo) {
    uint32_t h;
    asm("cvt.rna.tf32.f32 %0, %1;" : "=r"(h) : "f"(f));
    float hf = __uint_as_float(h);
    float lf = f - hf;
    asm("cvt.rna.tf32.f32 %0, %1;" : "=r"(lo) : "f"(lf));
    hi = h;
}

__device__ __forceinline__ void mma_tf32(float c[4], const uint32_t a[4], uint32_t b0, uint32_t b1) {
    asm volatile(
        "mma.sync.aligned.m16n8k8.row.col.f32.tf32.tf32.f32 "
        "{%0,%1,%2,%3}, {%4,%5,%6,%7}, {%8,%9}, {%0,%1,%2,%3};"
        : "+f"(c[0]), "+f"(c[1]), "+f"(c[2]), "+f"(c[3])
        : "r"(a[0]), "r"(a[1]), "r"(a[2]), "r"(a[3]), "r"(b0), "r"(b1));
}

// ---------------------------------------------------------------------------
// Kernel 0: fused prep — CSR rowptr from sorted edge_dst + W tf32 split
//   (wsplit rides along in the first 8192 threads; rowptr is latency-bound)
// ---------------------------------------------------------------------------
__global__ void prep_kernel(const int* __restrict__ edge_dst,
                            int* __restrict__ rowptr,
                            const float* __restrict__ W,
                            uint2* __restrict__ whp,
                            uint2* __restrict__ wlp) {
    int e = blockIdx.x * blockDim.x + threadIdx.x;
    if (e < N_EDGES) {
        int d = __ldg(&edge_dst[e]);
        if (e == 0) {
            for (int n = 0; n <= d; n++) rowptr[n] = 0;
        } else {
            int dp = __ldg(&edge_dst[e - 1]);
            for (int n = dp + 1; n <= d; n++) rowptr[n] = e;
        }
        if (e == N_EDGES - 1) {
            for (int n = d + 1; n <= N_NODES; n++) rowptr[n] = N_EDGES;
        }
    }
    if (e < D_OUT * (D_IN / 8) * 4) {   // 8192
        int n   = e >> 7;        // 0..63
        int rem = e & 127;
        int kb  = rem >> 2;      // 0..31
        int tq  = rem & 3;       // 0..3
        float w0 = __ldg(&W[n * D_IN + kb * 8 + tq]);
        float w1 = __ldg(&W[n * D_IN + kb * 8 + tq + 4]);
        uint32_t h0, l0, h1, l1;
        tf32_split(w0, h0, l0);
        tf32_split(w1, h1, l1);
        whp[e] = make_uint2(h0, h1);
        wlp[e] = make_uint2(l0, l1);
    }
}

// ---------------------------------------------------------------------------
// Kernel 1: support = x @ W^T + b  via tf32 tensor cores (3xTF32)
//   Block: 128 threads (4 warps), 128 rows. Warp: 32 rows (two m16 tiles) x 64 cols.
//   K_CHUNK = 16. B fragments: single conflict-free LDS.64 from paired layout.
//   smem: xs 10.2KB + wh/wl 12.3KB = 22.5KB.
// ---------------------------------------------------------------------------
#define KC 16

__global__ __launch_bounds__(128) void gemm_tf32_kernel(
    const float* __restrict__ x,
    const uint2* __restrict__ whp,
    const uint2* __restrict__ wlp,
    const float* __restrict__ bias,
    float* __restrict__ support)
{
    __shared__ float xs[128][20];     // [row][k], stride 20 -> conflict-free frag reads
    __shared__ uint2 wh_s[64][12];    // [n][kbl*4+tq], stride 12 uint2 (96B, 16B-aligned)
    __shared__ uint2 wl_s[64][12];

    const int tid  = threadIdx.x;
    const int warp = tid >> 5;    // 0..3
    const int lane = tid & 31;
    const int gq   = lane >> 2;   // 0..7
    const int tq   = lane & 3;    // 0..3
    const int row_base = blockIdx.x * 128;

    float acc[2][8][4];
    #pragma unroll
    for (int t = 0; t < 2; t++)
        #pragma unroll
        for (int nt = 0; nt < 8; nt++)
            #pragma unroll
            for (int j = 0; j < 4; j++) acc[t][nt][j] = 0.f;

    for (int kt = 0; kt < D_IN; kt += KC) {
        const int kb0 = kt >> 3;
        // stage x tile [128][16]: 512 float4, 4 per thread
        #pragma unroll
        for (int i = 0; i < 4; i++) {
            int idx = tid + i * 128;
            int r   = idx >> 2;
            int c4  = idx & 3;
            int gr  = row_base + r;
            float4 v = make_float4(0.f, 0.f, 0.f, 0.f);
            if (gr < N_NODES)
                v = *(const float4*)&x[(size_t)gr * D_IN + kt + c4 * 4];
            *(float4*)&xs[r][c4 * 4] = v;
        }
        // stage W pair tiles: 256 uint4 each, 2 per thread each
        #pragma unroll
        for (int i = 0; i < 2; i++) {
            int idx = tid + i * 128;
            int n   = idx >> 2;
            int q   = idx & 3;
            ((uint4*)&wh_s[n][0])[q] = ((const uint4*)whp)[n * 64 + kb0 * 2 + q];
            ((uint4*)&wl_s[n][0])[q] = ((const uint4*)wlp)[n * 64 + kb0 * 2 + q];
        }
        __syncthreads();

        #pragma unroll
        for (int kbl = 0; kbl < 2; kbl++) {
            const int k8 = kbl * 8;
            // A fragments for the two 16-row tiles
            uint32_t ah[2][4], al[2][4];
            #pragma unroll
            for (int t = 0; t < 2; t++) {
                const int r0 = warp * 32 + t * 16 + gq;
                float a0 = xs[r0    ][k8 + tq];
                float a1 = xs[r0 + 8][k8 + tq];
                float a2 = xs[r0    ][k8 + tq + 4];
                float a3 = xs[r0 + 8][k8 + tq + 4];
                tf32_split(a0, ah[t][0], al[t][0]);
                tf32_split(a1, ah[t][1], al[t][1]);
                tf32_split(a2, ah[t][2], al[t][2]);
                tf32_split(a3, ah[t][3], al[t][3]);
            }
            #pragma unroll
            for (int nt = 0; nt < 8; nt++) {
                const int n0 = nt * 8 + gq;
                uint2 bh = wh_s[n0][kbl * 4 + tq];
                uint2 bl = wl_s[n0][kbl * 4 + tq];
                mma_tf32(acc[0][nt], ah[0], bh.x, bh.y);   // hi*hi
                mma_tf32(acc[0][nt], ah[0], bl.x, bl.y);   // hi*lo
                mma_tf32(acc[0][nt], al[0], bh.x, bh.y);   // lo*hi
                mma_tf32(acc[1][nt], ah[1], bh.x, bh.y);
                mma_tf32(acc[1][nt], ah[1], bl.x, bl.y);
                mma_tf32(acc[1][nt], al[1], bh.x, bh.y);
            }
        }
        __syncthreads();
    }

    // Epilogue
    #pragma unroll
    for (int t = 0; t < 2; t++) {
        const int r_lo = row_base + warp * 32 + t * 16 + gq;
        const int r_hi = r_lo + 8;
        #pragma unroll
        for (int nt = 0; nt < 8; nt++) {
            int c0 = nt * 8 + tq * 2;
            float bx = bias[c0], by = bias[c0 + 1];
            if (r_lo < N_NODES) {
                float2 v = make_float2(acc[t][nt][0] + bx, acc[t][nt][1] + by);
                *(float2*)&support[(size_t)r_lo * D_OUT + c0] = v;
            }
            if (r_hi < N_NODES) {
                float2 v = make_float2(acc[t][nt][2] + bx, acc[t][nt][3] + by);
                *(float2*)&support[(size_t)r_hi * D_OUT + c0] = v;
            }
        }
    }
}

// ---------------------------------------------------------------------------
// Kernel 2: aggregation + LeakyReLU. Half-warp per node, float4 lanes.
//   Lane owns 4 columns; warp handles 2 nodes. No atomics, direct store.
// ---------------------------------------------------------------------------
__global__ __launch_bounds__(256) void agg_node_kernel(
    const int*    __restrict__ edge_src,
    const float*  __restrict__ edge_val,
    const int*    __restrict__ rowptr,
    const float4* __restrict__ support4,
    float4*       __restrict__ out4)
{
    const int warpid = (blockIdx.x * blockDim.x + threadIdx.x) >> 5;
    const int lane   = threadIdx.x & 31;
    const int node   = warpid * 2 + (lane >> 4);
    const int c4     = lane & 15;
    if (node >= N_NODES) return;

    const int beg = __ldg(&rowptr[node]);
    const int end = __ldg(&rowptr[node + 1]);

    float4 acc = make_float4(0.f, 0.f, 0.f, 0.f);
    #pragma unroll 4
    for (int e = beg; e < end; e++) {
        const int   s = __ldg(&edge_src[e]);     // uniform within half-warp
        const float v = __ldg(&edge_val[e]);
        float4 sv = __ldg(&support4[(size_t)s * 16 + c4]);
        acc.x += v * sv.x;
        acc.y += v * sv.y;
        acc.z += v * sv.z;
        acc.w += v * sv.w;
    }
    acc.x = (acc.x >= 0.f) ? acc.x : NEG_SLOPE * acc.x;
    acc.y = (acc.y >= 0.f) ? acc.y : NEG_SLOPE * acc.y;
    acc.z = (acc.z >= 0.f) ? acc.z : NEG_SLOPE * acc.z;
    acc.w = (acc.w >= 0.f) ? acc.w : NEG_SLOPE * acc.w;
    out4[(size_t)node * 16 + c4] = acc;
}

// ---------------------------------------------------------------------------
// Launch
// ---------------------------------------------------------------------------
extern "C" void kernel_launch(void* const* d_in, const int* in_sizes, int n_in,
                              void* d_out, int out_size) {
    const float* x        = (const float*)d_in[0];
    const float* W        = (const float*)d_in[1];
    const float* b        = (const float*)d_in[2];
    const int*   edge_src = (const int*)  d_in[3];
    const int*   edge_dst = (const int*)  d_in[4];
    const float* edge_val = (const float*)d_in[5];
    float* out = (float*)d_out;

    float* support;
    cudaGetSymbolAddress((void**)&support, g_support);
    int* rowptr;
    cudaGetSymbolAddress((void**)&rowptr, g_rowptr);
    uint2* whp;
    cudaGetSymbolAddress((void**)&whp, g_whp);
    uint2* wlp;
    cudaGetSymbolAddress((void**)&wlp, g_wlp);

    // 0. fused prep: rowptr + W tf32 split (paired layout)
    prep_kernel<<<(N_EDGES + 255) / 256, 256>>>(edge_dst, rowptr, W, whp, wlp);

    // 1. tf32 tensor-core projection
    gemm_tf32_kernel<<<(N_NODES + 127) / 128, 128>>>(x, whp, wlp, b, support);

    // 2. fused aggregation + LeakyReLU (half-warp per node)
    const int n_warps  = (N_NODES + 1) / 2;            // 25000
    const int n_blocks = (n_warps * 32 + 255) / 256;   // 3125
    agg_node_kernel<<<n_blocks, 256>>>(edge_src, edge_val, rowptr,
                                       (const float4*)support, (float4*)out);
}